// round 8
// baseline (speedup 1.0000x reference)
#include <cuda_runtime.h>

// PLIF spiking neuron forward — round 8: 8-deep v8 bursts, software-pipelined.
// x: [B=16, T=32, C=128, H=32, W=32] fp32; a scalar; out spikes fp32 {0,1}.
//
// Burst-depth dose-response saturated at 8 (73.0% @2KB, 74.6% @4KB,
// 76.4% @8KB, 74.4% @16KB — the 16 case starved reads during its long
// store phase at 16.6% occ). This round keeps the optimal 8-deep burst but
// prefetches the NEXT chunk's 8 LDG.E.256 before storing the current chunk,
// so every warp always has a full read burst in flight while its writes
// drain — read-stream density no longer depends on occupancy.

constexpr int B = 16;
constexpr int T = 32;
constexpr int C = 128;
constexpr int H = 32;
constexpr int W = 32;
constexpr int CHW      = C * H * W;          // 131072 floats per (b,t) slice
constexpr int CHW_V8   = CHW / 8;            // 16384 v8 chunks per slice
constexpr int TOTAL_V8 = B * CHW_V8;         // 262144 v8 sites
constexpr int DEPTH    = 8;                  // t-steps per burst
constexpr int NCHUNK   = T / DEPTH;          // 4

__device__ __forceinline__ void ldg256_cs(const float* p, float* v)
{
    asm volatile(
        "ld.global.cs.v8.f32 {%0,%1,%2,%3,%4,%5,%6,%7}, [%8];"
        : "=f"(v[0]), "=f"(v[1]), "=f"(v[2]), "=f"(v[3]),
          "=f"(v[4]), "=f"(v[5]), "=f"(v[6]), "=f"(v[7])
        : "l"(p));
}

__device__ __forceinline__ void stg256_cs(float* p, const float* v)
{
    asm volatile(
        "st.global.cs.v8.f32 [%0], {%1,%2,%3,%4,%5,%6,%7,%8};"
        :: "l"(p),
           "f"(v[0]), "f"(v[1]), "f"(v[2]), "f"(v[3]),
           "f"(v[4]), "f"(v[5]), "f"(v[6]), "f"(v[7])
        : "memory");
}

__global__ __launch_bounds__(128)
void plif_fwd_kernel(const float* __restrict__ x,
                     const float* __restrict__ a,
                     float*       __restrict__ out)
{
    int i = blockIdx.x * blockDim.x + threadIdx.x;
    if (i >= TOTAL_V8) return;

    int b    = i >> 14;                // i / CHW_V8
    int chw8 = i & (CHW_V8 - 1);
    long long base = (long long)b * (T * CHW) + (long long)chw8 * 8;

    float av = __ldg(a);
    float decay = 1.0f / (1.0f + expf(-av));

    float mem[8];
    #pragma unroll
    for (int e = 0; e < 8; e++) mem[e] = 0.0f;

    float xi[2][DEPTH][8];

    // Prologue: first read burst.
    #pragma unroll
    for (int u = 0; u < DEPTH; u++)
        ldg256_cs(x + base + (long long)u * CHW, xi[0][u]);

    #pragma unroll
    for (int c = 0; c < NCHUNK; c++) {
        const int cur = c & 1;
        const int nxt = cur ^ 1;

        // Prefetch next chunk's read burst BEFORE any dependent work /
        // store burst of the current chunk — reads never go dry.
        if (c + 1 < NCHUNK) {
            #pragma unroll
            for (int u = 0; u < DEPTH; u++)
                ldg256_cs(x + base + (long long)((c + 1) * DEPTH + u) * CHW,
                          xi[nxt][u]);
        }

        // Recurrence + spike + hard reset; spikes overwrite xi in place.
        #pragma unroll
        for (int u = 0; u < DEPTH; u++) {
            #pragma unroll
            for (int e = 0; e < 8; e++) {
                mem[e] = fmaf(decay, mem[e], xi[cur][u][e]);
                bool fire = (mem[e] >= 1.0f);
                xi[cur][u][e] = fire ? 1.0f : 0.0f;
                mem[e]        = fire ? 0.0f : mem[e];
            }
        }

        // Write burst (8 back-to-back STG.E.256) — next reads already queued.
        #pragma unroll
        for (int u = 0; u < DEPTH; u++)
            stg256_cs(out + base + (long long)(c * DEPTH + u) * CHW, xi[cur][u]);
    }
}

extern "C" void kernel_launch(void* const* d_in, const int* in_sizes, int n_in,
                              void* d_out, int out_size)
{
    const float* x   = (const float*)d_in[0];
    const float* a   = (const float*)d_in[1];
    float*       out = (float*)d_out;

    constexpr int THREADS = 128;
    constexpr int BLOCKS  = (TOTAL_V8 + THREADS - 1) / THREADS;  // 2048

    plif_fwd_kernel<<<BLOCKS, THREADS>>>(x, a, out);
}